// round 11
// baseline (speedup 1.0000x reference)
#include <cuda_runtime.h>
#include <cuda_bf16.h>
#include <stdint.h>

#define NN 4096
#define NB 16
#define ND 64

// GEMM tiling: C[4096,1024] = W[4096,4096] @ Xt^T, Xt[n=b*64+d][k]
#define BM 128
#define BN 128
#define BK 64
#define STAGES 3
#define KT (NN / BK)                 // 64
#define ASTR 72                      // padded row stride (elems): 144B, %16==0
#define TILE_B (128 * ASTR * 2)      // 18432 bytes per tile (A or B)
#define STAGE_B (2 * TILE_B)         // 36864
#define SMEM_B (STAGES * STAGE_B)    // 110592

// ---------------- scratch (device globals: allocation-free) ----------------
static __device__ __align__(16) __nv_bfloat16 g_Wbf[(size_t)NN * NN];        // 32 MB, diag=0
static __device__ __align__(16) __nv_bfloat16 g_Xt[(size_t)NB * ND * NN];    // 8 MB, [b*64+d][k]
static __device__ __align__(16) float         g_Xproj[(size_t)NB * NN * ND]; // 16.8 MB
static __device__ float2        g_l12[NN];

// ---------------- PTX helpers ----------------------------------------------
#define CP_ASYNC16(dst, src) \
    asm volatile("cp.async.cg.shared.global [%0], [%1], 16;" :: "r"(dst), "l"(src))
#define CP_COMMIT() asm volatile("cp.async.commit_group;" ::: "memory")
#define CP_WAIT(n)  asm volatile("cp.async.wait_group %0;" :: "n"(n) : "memory")

__device__ __forceinline__ uint32_t smem_u32(const void* p) {
    uint32_t a;
    asm("{ .reg .u64 t; cvta.to.shared.u64 t, %1; cvt.u32.u64 %0, t; }" : "=r"(a) : "l"(p));
    return a;
}
__device__ __forceinline__ void ldsm4(uint32_t a, uint32_t& r0, uint32_t& r1, uint32_t& r2, uint32_t& r3) {
    asm volatile("ldmatrix.sync.aligned.m8n8.x4.shared.b16 {%0,%1,%2,%3},[%4];"
                 : "=r"(r0), "=r"(r1), "=r"(r2), "=r"(r3) : "r"(a));
}
__device__ __forceinline__ void mma_bf16(float* c, uint32_t a0, uint32_t a1, uint32_t a2, uint32_t a3,
                                         uint32_t b0, uint32_t b1) {
    asm volatile(
        "mma.sync.aligned.m16n8k16.row.col.f32.bf16.bf16.f32 "
        "{%0,%1,%2,%3}, {%4,%5,%6,%7}, {%8,%9}, {%0,%1,%2,%3};"
        : "+f"(c[0]), "+f"(c[1]), "+f"(c[2]), "+f"(c[3])
        : "r"(a0), "r"(a1), "r"(a2), "r"(a3), "r"(b0), "r"(b1));
}
__device__ __forceinline__ uint32_t pack_bf2(float a, float b) {
    __nv_bfloat162 p = __floats2bfloat162_rn(a, b);
    return *(uint32_t*)&p;
}
__device__ __forceinline__ float th(float v) { return (v > 0.01f) ? v : 0.0f; }

// ---------------- kernel 1: threshold/scatter W, incidence_all, l1/l2 ------
// Thread t owns output cols [16t, 16t+16). Input row length is NN-1 (odd row
// stride!), so the row base is only 4B-aligned; m = rowstart&3 is uniform per
// block. Interior threads read a 6-quad ALIGNED window and gather at constant
// indices selected by a block-uniform switch. Scalar fallback: diag chunk, t=255.
__global__ void __launch_bounds__(256) k_prep(const float* __restrict__ inc,
                                              float* __restrict__ inc_all) {
    const int i = blockIdx.x;
    const int t = threadIdx.x;
    const int base = t * 16;
    const float* row = inc + (size_t)i * (NN - 1);
    float* orow = inc_all + (size_t)i * NN;
    __nv_bfloat16* wrow = g_Wbf + (size_t)i * NN;

    const int m = (int)(((size_t)i * (size_t)(NN - 1)) & 3u);  // float misalignment of row base
    const bool diag_here = ((unsigned)(i - base) < 16u);

    float wv[16];

    if (!diag_here && t != 255) {
        // 6 aligned quads covering row[base-4-m .. base+20-m)
        float w24[24];
        const float* ap = row + base - 4 - m;   // 16B-aligned by construction
        #pragma unroll
        for (int q = 0; q < 6; q++) {
            float4 v = *(const float4*)(ap + 4 * q);
            w24[4 * q + 0] = v.x; w24[4 * q + 1] = v.y;
            w24[4 * q + 2] = v.z; w24[4 * q + 3] = v.w;
        }
        // left of diag: wv[k] = th(in[base+k])   = w24[4+m+k]
        // right of diag: wv[k] = th(in[base-1+k]) = w24[3+m+k]
        const int sh = m + ((base > i) ? 3 : 4);   // in {3..7}, block-uniform
        #define GATHER(S) { _Pragma("unroll") \
            for (int k = 0; k < 16; k++) wv[k] = th(w24[(S) + k]); }
        switch (sh) {
            case 3: GATHER(3); break;
            case 4: GATHER(4); break;
            case 5: GATHER(5); break;
            case 6: GATHER(6); break;
            default: GATHER(7); break;
        }
        #undef GATHER
    } else {
        // scalar fallback (diag chunk / last thread)
        #pragma unroll
        for (int k = 0; k < 16; k++) {
            const int fc = base + k;
            wv[k] = (fc == i) ? 0.0f : th(row[fc - (fc > i)]);
        }
    }

    // stats over this chunk (diag slot holds 0 -> no effect)
    float lmax = 0.0f, lsq = 0.0f;
    #pragma unroll
    for (int k = 0; k < 16; k++) {
        lmax = fmaxf(lmax, wv[k]);
        lsq += wv[k] * wv[k];
    }

    // W bf16 store: 16 bf16 = 2 x 16B (wrow+base is 32B-aligned)
    {
        uint4 u0, u1;
        u0.x = pack_bf2(wv[0],  wv[1]);  u0.y = pack_bf2(wv[2],  wv[3]);
        u0.z = pack_bf2(wv[4],  wv[5]);  u0.w = pack_bf2(wv[6],  wv[7]);
        u1.x = pack_bf2(wv[8],  wv[9]);  u1.y = pack_bf2(wv[10], wv[11]);
        u1.z = pack_bf2(wv[12], wv[13]); u1.w = pack_bf2(wv[14], wv[15]);
        *(uint4*)(wrow + base)     = u0;
        *(uint4*)(wrow + base + 8) = u1;
    }

    // inc_all fp32 store with diag = 1
    if (diag_here) wv[i - base] = 1.0f;
    #pragma unroll
    for (int q = 0; q < 4; q++)
        *(float4*)(orow + base + 4 * q) =
            make_float4(wv[4 * q], wv[4 * q + 1], wv[4 * q + 2], wv[4 * q + 3]);

    // row reduction
    #pragma unroll
    for (int o = 16; o > 0; o >>= 1) {
        lmax = fmaxf(lmax, __shfl_xor_sync(0xffffffffu, lmax, o));
        lsq += __shfl_xor_sync(0xffffffffu, lsq, o);
    }
    __shared__ float sm[8], ss[8];
    int wid = t >> 5, lane = t & 31;
    if (lane == 0) { sm[wid] = lmax; ss[wid] = lsq; }
    __syncthreads();
    if (t == 0) {
        float mx = sm[0], q = ss[0];
        #pragma unroll
        for (int k = 1; k < 8; k++) { mx = fmaxf(mx, sm[k]); q += ss[k]; }
        g_l12[i] = make_float2(mx, sqrtf(q));
    }
}

// ---------------- kernel 2: transpose X -> Xt bf16 [b*64+d][k] -------------
#define XS 68   // row stride (floats): 272B, multiple of 16 -> aligned float4
__global__ void k_xt(const float* __restrict__ X) {
    __shared__ __align__(16) float s[64 * XS];
    int k0 = blockIdx.x * 64, b = blockIdx.y;
    int t = threadIdx.x;
    {
        int tr = t >> 2, tc = (t & 3) * 16;
        const float* src = X + ((size_t)b * NN + k0 + tr) * ND + tc;
        float4 v0 = ((const float4*)src)[0];
        float4 v1 = ((const float4*)src)[1];
        float4 v2 = ((const float4*)src)[2];
        float4 v3 = ((const float4*)src)[3];
        float* sr = s + tr * XS + tc;
        *(float4*)(sr + 0)  = v0;
        *(float4*)(sr + 4)  = v1;
        *(float4*)(sr + 8)  = v2;
        *(float4*)(sr + 12) = v3;
    }
    __syncthreads();
    {
        int d = t >> 2, kc = (t & 3) * 16;
        const float* sc = s + kc * XS + d;
        uint4 u0, u1;
        u0.x = pack_bf2(sc[0 * XS],  sc[1 * XS]);
        u0.y = pack_bf2(sc[2 * XS],  sc[3 * XS]);
        u0.z = pack_bf2(sc[4 * XS],  sc[5 * XS]);
        u0.w = pack_bf2(sc[6 * XS],  sc[7 * XS]);
        u1.x = pack_bf2(sc[8 * XS],  sc[9 * XS]);
        u1.y = pack_bf2(sc[10 * XS], sc[11 * XS]);
        u1.z = pack_bf2(sc[12 * XS], sc[13 * XS]);
        u1.w = pack_bf2(sc[14 * XS], sc[15 * XS]);
        __nv_bfloat16* dst = g_Xt + ((size_t)b * ND + d) * NN + k0 + kc;
        ((uint4*)dst)[0] = u0;
        ((uint4*)dst)[1] = u1;
    }
}

// ---------------- kernel 3: X_proj = X @ r_proj (fp32 exact) ---------------
__global__ void k_xproj(const float* __restrict__ X, const float* __restrict__ rp) {
    __shared__ float rps[ND * ND];
    for (int t = threadIdx.x; t < ND * ND / 4; t += blockDim.x)
        ((float4*)rps)[t] = ((const float4*)rp)[t];
    __syncthreads();

    int gt = blockIdx.x * blockDim.x + threadIdx.x;
    int row = gt >> 2;
    int d0 = (gt & 3) * 16;
    const float* xr = X + (size_t)row * ND;

    float acc[16];
    #pragma unroll
    for (int i = 0; i < 16; i++) acc[i] = 0.0f;

    #pragma unroll 4
    for (int e = 0; e < ND; e++) {
        float xe = __ldg(&xr[e]);
        const float* rr = rps + e * ND + d0;
        #pragma unroll
        for (int i = 0; i < 16; i++) acc[i] += xe * rr[i];
    }
    float* o = g_Xproj + (size_t)row * ND + d0;
    #pragma unroll
    for (int i = 0; i < 4; i++)
        ((float4*)o)[i] = make_float4(acc[4*i], acc[4*i+1], acc[4*i+2], acc[4*i+3]);
}

// ---------------- kernel 4: HMMA GEMM (fused N=1024) + loss epilogue -------
// 256 threads, 8 warps 2x4 (warp tile 64x32); BK=64, 3-stage cp.async pipeline.
__global__ void __launch_bounds__(256, 2) k_gemm(float* __restrict__ out_loss) {
    extern __shared__ char dsm[];
    const uint32_t sbase = smem_u32(dsm);

    const int tid = threadIdx.x, wid = tid >> 5, lane = tid & 31;
    const int wm = wid >> 2, wn = wid & 3;           // 2x4 warps, 64x32 each
    const int mbase = wm * 64, nbase = wn * 32;
    const int g = lane >> 2, t4 = lane & 3;
    const int lrow = lane & 15, lcol = (lane >> 4) * 8;

    const int m0 = blockIdx.x * BM;
    const int n0 = blockIdx.y * BN;                  // n = b*64+d space

    const __nv_bfloat16* Ag = g_Wbf + (size_t)m0 * NN;
    const __nv_bfloat16* Bg = g_Xt + (size_t)n0 * NN;

    const int ldrow = tid >> 3;            // 0..31 (+32i)
    const int ldcol = (tid & 7) * 8;       // 0..56
    const uint32_t ld_off = (uint32_t)(ldrow * (ASTR * 2) + ldcol * 2);

    const uint32_t a_inv = (uint32_t)((mbase + lrow) * (ASTR * 2) + lcol * 2);
    const uint32_t b_inv = (uint32_t)((nbase + lrow) * (ASTR * 2) + lcol * 2) + TILE_B;

    #define LOAD_STAGE(sb_, kc_) do {                                        \
        const __nv_bfloat16* _ag = Ag + (size_t)(kc_) * BK + ldcol;          \
        const __nv_bfloat16* _bg = Bg + (size_t)(kc_) * BK + ldcol;          \
        _Pragma("unroll")                                                    \
        for (int _i = 0; _i < 4; _i++) {                                     \
            int _r = ldrow + _i * 32;                                        \
            uint32_t _o = ld_off + (uint32_t)(_i * 32 * (ASTR * 2));         \
            CP_ASYNC16((sb_) + _o, _ag + (size_t)_r * NN);                   \
            CP_ASYNC16((sb_) + TILE_B + _o, _bg + (size_t)_r * NN);          \
        }                                                                    \
    } while (0)

    float acc[4][4][4];
    #pragma unroll
    for (int i = 0; i < 4; i++)
        #pragma unroll
        for (int j = 0; j < 4; j++)
            #pragma unroll
            for (int k = 0; k < 4; k++) acc[i][j][k] = 0.0f;

    LOAD_STAGE(sbase, 0);
    CP_COMMIT();
    LOAD_STAGE(sbase + STAGE_B, 1);
    CP_COMMIT();

    uint32_t soff = 0;
    uint32_t poff = 2 * STAGE_B;
    #pragma unroll 1
    for (int kt = 0; kt < KT; kt++) {
        CP_WAIT(1);
        __syncthreads();

        if (kt + 2 < KT) LOAD_STAGE(sbase + poff, kt + 2);
        CP_COMMIT();

        const uint32_t ab = sbase + soff + a_inv;
        const uint32_t bb = sbase + soff + b_inv;
        #pragma unroll
        for (int ks = 0; ks < 4; ks++) {
            const uint32_t kb = (uint32_t)(ks * 32);
            uint32_t ar[4][4], br[2][4];
            #pragma unroll
            for (int mf = 0; mf < 4; mf++)
                ldsm4(ab + kb + (uint32_t)(mf * 16 * (ASTR * 2)),
                      ar[mf][0], ar[mf][1], ar[mf][2], ar[mf][3]);
            #pragma unroll
            for (int p = 0; p < 2; p++)
                ldsm4(bb + kb + (uint32_t)(p * 16 * (ASTR * 2)),
                      br[p][0], br[p][1], br[p][2], br[p][3]);
            #pragma unroll
            for (int mf = 0; mf < 4; mf++)
                #pragma unroll
                for (int p = 0; p < 2; p++) {
                    mma_bf16(acc[mf][2 * p + 0], ar[mf][0], ar[mf][1], ar[mf][2], ar[mf][3],
                             br[p][0], br[p][2]);
                    mma_bf16(acc[mf][2 * p + 1], ar[mf][0], ar[mf][1], ar[mf][2], ar[mf][3],
                             br[p][1], br[p][3]);
                }
        }

        soff += STAGE_B; if (soff == STAGES * STAGE_B) soff = 0;
        poff += STAGE_B; if (poff == STAGES * STAGE_B) poff = 0;
    }

    // ---- epilogue ----
    const int b = (n0 + nbase) >> 6;
    const int dbase = nbase & 63;
    float rs[8];
    #pragma unroll
    for (int i = 0; i < 8; i++) rs[i] = 0.0f;

    #pragma unroll
    for (int mf = 0; mf < 4; mf++) {
        #pragma unroll
        for (int h = 0; h < 2; h++) {
            const int r = m0 + mbase + mf * 16 + h * 8 + g;
            const float* xp = g_Xproj + ((size_t)b * NN + r) * ND + dbase;
            float a = 0.0f;
            #pragma unroll
            for (int nf = 0; nf < 4; nf++) {
                float2 v = *(const float2*)(xp + nf * 8 + 2 * t4);
                float d0 = v.x - acc[mf][nf][h * 2 + 0];
                float d1 = v.y - acc[mf][nf][h * 2 + 1];
                a += d0 * d0 + d1 * d1;
            }
            rs[mf * 2 + h] = a;
        }
    }
    #pragma unroll
    for (int i = 0; i < 8; i++) {
        rs[i] += __shfl_xor_sync(0xffffffffu, rs[i], 1);
        rs[i] += __shfl_xor_sync(0xffffffffu, rs[i], 2);
    }

    __syncthreads();
    float* red = (float*)dsm;       // [wm][wn][64]
    if (t4 == 0) {
        #pragma unroll
        for (int i = 0; i < 8; i++) {
            const int rloc = (i >> 1) * 16 + (i & 1) * 8 + g;
            red[(wm * 4 + wn) * 64 + rloc] = rs[i];
        }
    }
    __syncthreads();
    {
        const int bsel = tid >> 7;
        const int rl = tid & 127;
        const int wmx = rl >> 6, rloc = rl & 63;
        const float s2 = red[(wmx * 4 + bsel * 2) * 64 + rloc] +
                         red[(wmx * 4 + bsel * 2 + 1) * 64 + rloc];
        const int row = m0 + rl;
        const int batch = blockIdx.y * 2 + bsel;
        const float2 l = g_l12[row];
        out_loss[(size_t)batch * NN + row] = 0.2f * sqrtf(s2) + l.x + 0.001f * l.y;
    }
}

// ---------------- launch ----------------------------------------------------
extern "C" void kernel_launch(void* const* d_in, const int* in_sizes, int n_in,
                              void* d_out, int out_size) {
    const float *X = nullptr, *rp = nullptr, *inc = nullptr;
    for (int i = 0; i < n_in; i++) {
        if (in_sizes[i] == NB * NN * ND)       X   = (const float*)d_in[i];
        else if (in_sizes[i] == ND * ND)       rp  = (const float*)d_in[i];
        else if (in_sizes[i] == NN * (NN - 1)) inc = (const float*)d_in[i];
    }
    float* out = (float*)d_out;
    float* loss = out;                           // [B, N]
    float* inc_all = out + (size_t)NB * NN;      // [N, N]

    cudaFuncSetAttribute(k_gemm, cudaFuncAttributeMaxDynamicSharedMemorySize, SMEM_B);

    k_prep<<<NN, 256>>>(inc, inc_all);
    k_xt<<<dim3(NN / 64, NB), 256>>>(X);
    k_xproj<<<(NB * NN * 4) / 256, 256>>>(X, rp);
    k_gemm<<<dim3(NN / BM, (NB * ND) / BN), 256, SMEM_B>>>(loss);
}

// round 12
// speedup vs baseline: 1.0007x; 1.0007x over previous
#include <cuda_runtime.h>
#include <cuda_bf16.h>
#include <stdint.h>

#define NN 4096
#define NB 16
#define ND 64

// GEMM tiling: C[4096,1024] = W[4096,4096] @ Xt^T, Xt[n=b*64+d][k]
#define BM 128
#define BN 128
#define BK 64
#define STAGES 3
#define KT (NN / BK)                 // 64
#define ASTR 72                      // padded row stride (elems): 144B, %16==0
#define TILE_B (128 * ASTR * 2)      // 18432 bytes per tile (A or B)
#define STAGE_B (2 * TILE_B)         // 36864
#define SMEM_B (STAGES * STAGE_B)    // 110592

// ---------------- scratch (device globals: allocation-free) ----------------
static __device__ __align__(16) __nv_bfloat16 g_Wbf[(size_t)NN * NN];        // 32 MB, diag=0
static __device__ __align__(16) __nv_bfloat16 g_Xt[(size_t)NB * ND * NN];    // 8 MB, [b*64+d][k]
static __device__ __align__(16) float         g_Xproj[(size_t)NB * NN * ND]; // 16.8 MB
static __device__ float2        g_l12[NN];

// ---------------- PTX helpers ----------------------------------------------
#define CP_ASYNC16(dst, src) \
    asm volatile("cp.async.cg.shared.global [%0], [%1], 16;" :: "r"(dst), "l"(src))
#define CP_COMMIT() asm volatile("cp.async.commit_group;" ::: "memory")
#define CP_WAIT(n)  asm volatile("cp.async.wait_group %0;" :: "n"(n) : "memory")

__device__ __forceinline__ uint32_t smem_u32(const void* p) {
    uint32_t a;
    asm("{ .reg .u64 t; cvta.to.shared.u64 t, %1; cvt.u32.u64 %0, t; }" : "=r"(a) : "l"(p));
    return a;
}
__device__ __forceinline__ void ldsm4(uint32_t a, uint32_t& r0, uint32_t& r1, uint32_t& r2, uint32_t& r3) {
    asm volatile("ldmatrix.sync.aligned.m8n8.x4.shared.b16 {%0,%1,%2,%3},[%4];"
                 : "=r"(r0), "=r"(r1), "=r"(r2), "=r"(r3) : "r"(a));
}
// NOTE: non-volatile on purpose — pure register dataflow; lets ptxas interleave
// HMMAs of step ks with LDSMs/cp.asyncs of step ks+1 (ordering enforced by
// register dependencies, not by the volatile fence).
__device__ __forceinline__ void mma_bf16(float* c, uint32_t a0, uint32_t a1, uint32_t a2, uint32_t a3,
                                         uint32_t b0, uint32_t b1) {
    asm("mma.sync.aligned.m16n8k16.row.col.f32.bf16.bf16.f32 "
        "{%0,%1,%2,%3}, {%4,%5,%6,%7}, {%8,%9}, {%0,%1,%2,%3};"
        : "+f"(c[0]), "+f"(c[1]), "+f"(c[2]), "+f"(c[3])
        : "r"(a0), "r"(a1), "r"(a2), "r"(a3), "r"(b0), "r"(b1));
}
__device__ __forceinline__ uint32_t pack_bf2(float a, float b) {
    __nv_bfloat162 p = __floats2bfloat162_rn(a, b);
    return *(uint32_t*)&p;
}

// ---------------- kernel 1: threshold/scatter W, incidence_all, l1/l2 ------
// (R9/best-measured version — scalar near-coalesced; prep is DRAM-bound, closed)
__global__ void k_prep(const float* __restrict__ inc, float* __restrict__ inc_all) {
    int i = blockIdx.x;
    const float* row = inc + (size_t)i * (NN - 1);
    float* orow = inc_all + (size_t)i * NN;
    __nv_bfloat16* wrow = g_Wbf + (size_t)i * NN;

    float lmax = 0.0f, lsq = 0.0f;
    for (int j = threadIdx.x; j < NN - 1; j += blockDim.x) {
        float v = row[j];
        float w = (v > 0.01f) ? v : 0.0f;
        int fc = j + (j >= i);
        orow[fc] = w;
        wrow[fc] = __float2bfloat16(w);
        lmax = fmaxf(lmax, w);
        lsq += w * w;
    }
    if (threadIdx.x == 0) {
        orow[i] = 1.0f;
        wrow[i] = __float2bfloat16(0.0f);
    }
    #pragma unroll
    for (int o = 16; o > 0; o >>= 1) {
        lmax = fmaxf(lmax, __shfl_xor_sync(0xffffffffu, lmax, o));
        lsq += __shfl_xor_sync(0xffffffffu, lsq, o);
    }
    __shared__ float sm[8], ss[8];
    int wid = threadIdx.x >> 5, lane = threadIdx.x & 31;
    if (lane == 0) { sm[wid] = lmax; ss[wid] = lsq; }
    __syncthreads();
    if (threadIdx.x == 0) {
        float m = sm[0], q = ss[0];
        #pragma unroll
        for (int k = 1; k < 8; k++) { m = fmaxf(m, sm[k]); q += ss[k]; }
        g_l12[i] = make_float2(m, sqrtf(q));
    }
}

// ---------------- kernel 2: transpose X -> Xt bf16 [b*64+d][k] -------------
#define XS 68   // row stride (floats): 272B, multiple of 16 -> aligned float4
__global__ void k_xt(const float* __restrict__ X) {
    __shared__ __align__(16) float s[64 * XS];
    int k0 = blockIdx.x * 64, b = blockIdx.y;
    int t = threadIdx.x;
    {
        int tr = t >> 2, tc = (t & 3) * 16;
        const float* src = X + ((size_t)b * NN + k0 + tr) * ND + tc;
        float4 v0 = ((const float4*)src)[0];
        float4 v1 = ((const float4*)src)[1];
        float4 v2 = ((const float4*)src)[2];
        float4 v3 = ((const float4*)src)[3];
        float* sr = s + tr * XS + tc;
        *(float4*)(sr + 0)  = v0;
        *(float4*)(sr + 4)  = v1;
        *(float4*)(sr + 8)  = v2;
        *(float4*)(sr + 12) = v3;
    }
    __syncthreads();
    {
        int d = t >> 2, kc = (t & 3) * 16;
        const float* sc = s + kc * XS + d;
        uint4 u0, u1;
        u0.x = pack_bf2(sc[0 * XS],  sc[1 * XS]);
        u0.y = pack_bf2(sc[2 * XS],  sc[3 * XS]);
        u0.z = pack_bf2(sc[4 * XS],  sc[5 * XS]);
        u0.w = pack_bf2(sc[6 * XS],  sc[7 * XS]);
        u1.x = pack_bf2(sc[8 * XS],  sc[9 * XS]);
        u1.y = pack_bf2(sc[10 * XS], sc[11 * XS]);
        u1.z = pack_bf2(sc[12 * XS], sc[13 * XS]);
        u1.w = pack_bf2(sc[14 * XS], sc[15 * XS]);
        __nv_bfloat16* dst = g_Xt + ((size_t)b * ND + d) * NN + k0 + kc;
        ((uint4*)dst)[0] = u0;
        ((uint4*)dst)[1] = u1;
    }
}

// ---------------- kernel 3: X_proj = X @ r_proj (fp32 exact) ---------------
__global__ void k_xproj(const float* __restrict__ X, const float* __restrict__ rp) {
    __shared__ float rps[ND * ND];
    for (int t = threadIdx.x; t < ND * ND / 4; t += blockDim.x)
        ((float4*)rps)[t] = ((const float4*)rp)[t];
    __syncthreads();

    int gt = blockIdx.x * blockDim.x + threadIdx.x;
    int row = gt >> 2;
    int d0 = (gt & 3) * 16;
    const float* xr = X + (size_t)row * ND;

    float acc[16];
    #pragma unroll
    for (int i = 0; i < 16; i++) acc[i] = 0.0f;

    #pragma unroll 4
    for (int e = 0; e < ND; e++) {
        float xe = __ldg(&xr[e]);
        const float* rr = rps + e * ND + d0;
        #pragma unroll
        for (int i = 0; i < 16; i++) acc[i] += xe * rr[i];
    }
    float* o = g_Xproj + (size_t)row * ND + d0;
    #pragma unroll
    for (int i = 0; i < 4; i++)
        ((float4*)o)[i] = make_float4(acc[4*i], acc[4*i+1], acc[4*i+2], acc[4*i+3]);
}

// ---------------- kernel 4: HMMA GEMM (fused N=1024) + loss epilogue -------
// 256 threads, 8 warps 2x4 (warp tile 64x32); BK=64, 3-stage cp.async pipeline.
__global__ void __launch_bounds__(256, 2) k_gemm(float* __restrict__ out_loss) {
    extern __shared__ char dsm[];
    const uint32_t sbase = smem_u32(dsm);

    const int tid = threadIdx.x, wid = tid >> 5, lane = tid & 31;
    const int wm = wid >> 2, wn = wid & 3;           // 2x4 warps, 64x32 each
    const int mbase = wm * 64, nbase = wn * 32;
    const int g = lane >> 2, t4 = lane & 3;
    const int lrow = lane & 15, lcol = (lane >> 4) * 8;

    const int m0 = blockIdx.x * BM;
    const int n0 = blockIdx.y * BN;                  // n = b*64+d space

    const __nv_bfloat16* Ag = g_Wbf + (size_t)m0 * NN;
    const __nv_bfloat16* Bg = g_Xt + (size_t)n0 * NN;

    const int ldrow = tid >> 3;            // 0..31 (+32i)
    const int ldcol = (tid & 7) * 8;       // 0..56
    const uint32_t ld_off = (uint32_t)(ldrow * (ASTR * 2) + ldcol * 2);

    const uint32_t a_inv = (uint32_t)((mbase + lrow) * (ASTR * 2) + lcol * 2);
    const uint32_t b_inv = (uint32_t)((nbase + lrow) * (ASTR * 2) + lcol * 2) + TILE_B;

    #define LOAD_STAGE(sb_, kc_) do {                                        \
        const __nv_bfloat16* _ag = Ag + (size_t)(kc_) * BK + ldcol;          \
        const __nv_bfloat16* _bg = Bg + (size_t)(kc_) * BK + ldcol;          \
        _Pragma("unroll")                                                    \
        for (int _i = 0; _i < 4; _i++) {                                     \
            int _r = ldrow + _i * 32;                                        \
            uint32_t _o = ld_off + (uint32_t)(_i * 32 * (ASTR * 2));         \
            CP_ASYNC16((sb_) + _o, _ag + (size_t)_r * NN);                   \
            CP_ASYNC16((sb_) + TILE_B + _o, _bg + (size_t)_r * NN);          \
        }                                                                    \
    } while (0)

    float acc[4][4][4];
    #pragma unroll
    for (int i = 0; i < 4; i++)
        #pragma unroll
        for (int j = 0; j < 4; j++)
            #pragma unroll
            for (int k = 0; k < 4; k++) acc[i][j][k] = 0.0f;

    LOAD_STAGE(sbase, 0);
    CP_COMMIT();
    LOAD_STAGE(sbase + STAGE_B, 1);
    CP_COMMIT();

    uint32_t soff = 0;
    uint32_t poff = 2 * STAGE_B;
    #pragma unroll 1
    for (int kt = 0; kt < KT; kt++) {
        CP_WAIT(1);
        __syncthreads();

        if (kt + 2 < KT) LOAD_STAGE(sbase + poff, kt + 2);
        CP_COMMIT();

        const uint32_t ab = sbase + soff + a_inv;
        const uint32_t bb = sbase + soff + b_inv;
        #pragma unroll
        for (int ks = 0; ks < 4; ks++) {
            const uint32_t kb = (uint32_t)(ks * 32);
            uint32_t ar[4][4], br[2][4];
            #pragma unroll
            for (int mf = 0; mf < 4; mf++)
                ldsm4(ab + kb + (uint32_t)(mf * 16 * (ASTR * 2)),
                      ar[mf][0], ar[mf][1], ar[mf][2], ar[mf][3]);
            #pragma unroll
            for (int p = 0; p < 2; p++)
                ldsm4(bb + kb + (uint32_t)(p * 16 * (ASTR * 2)),
                      br[p][0], br[p][1], br[p][2], br[p][3]);
            #pragma unroll
            for (int mf = 0; mf < 4; mf++)
                #pragma unroll
                for (int p = 0; p < 2; p++) {
                    mma_bf16(acc[mf][2 * p + 0], ar[mf][0], ar[mf][1], ar[mf][2], ar[mf][3],
                             br[p][0], br[p][2]);
                    mma_bf16(acc[mf][2 * p + 1], ar[mf][0], ar[mf][1], ar[mf][2], ar[mf][3],
                             br[p][1], br[p][3]);
                }
        }

        soff += STAGE_B; if (soff == STAGES * STAGE_B) soff = 0;
        poff += STAGE_B; if (poff == STAGES * STAGE_B) poff = 0;
    }

    // ---- epilogue ----
    const int b = (n0 + nbase) >> 6;
    const int dbase = nbase & 63;
    float rs[8];
    #pragma unroll
    for (int i = 0; i < 8; i++) rs[i] = 0.0f;

    #pragma unroll
    for (int mf = 0; mf < 4; mf++) {
        #pragma unroll
        for (int h = 0; h < 2; h++) {
            const int r = m0 + mbase + mf * 16 + h * 8 + g;
            const float* xp = g_Xproj + ((size_t)b * NN + r) * ND + dbase;
            float a = 0.0f;
            #pragma unroll
            for (int nf = 0; nf < 4; nf++) {
                float2 v = *(const float2*)(xp + nf * 8 + 2 * t4);
                float d0 = v.x - acc[mf][nf][h * 2 + 0];
                float d1 = v.y - acc[mf][nf][h * 2 + 1];
                a += d0 * d0 + d1 * d1;
            }
            rs[mf * 2 + h] = a;
        }
    }
    #pragma unroll
    for (int i = 0; i < 8; i++) {
        rs[i] += __shfl_xor_sync(0xffffffffu, rs[i], 1);
        rs[i] += __shfl_xor_sync(0xffffffffu, rs[i], 2);
    }

    __syncthreads();
    float* red = (float*)dsm;       // [wm][wn][64]
    if (t4 == 0) {
        #pragma unroll
        for (int i = 0; i < 8; i++) {
            const int rloc = (i >> 1) * 16 + (i & 1) * 8 + g;
            red[(wm * 4 + wn) * 64 + rloc] = rs[i];
        }
    }
    __syncthreads();
    {
        const int bsel = tid >> 7;
        const int rl = tid & 127;
        const int wmx = rl >> 6, rloc = rl & 63;
        const float s2 = red[(wmx * 4 + bsel * 2) * 64 + rloc] +
                         red[(wmx * 4 + bsel * 2 + 1) * 64 + rloc];
        const int row = m0 + rl;
        const int batch = blockIdx.y * 2 + bsel;
        const float2 l = g_l12[row];
        out_loss[(size_t)batch * NN + row] = 0.2f * sqrtf(s2) + l.x + 0.001f * l.y;
    }
}

// ---------------- launch ----------------------------------------------------
extern "C" void kernel_launch(void* const* d_in, const int* in_sizes, int n_in,
                              void* d_out, int out_size) {
    const float *X = nullptr, *rp = nullptr, *inc = nullptr;
    for (int i = 0; i < n_in; i++) {
        if (in_sizes[i] == NB * NN * ND)       X   = (const float*)d_in[i];
        else if (in_sizes[i] == ND * ND)       rp  = (const float*)d_in[i];
        else if (in_sizes[i] == NN * (NN - 1)) inc = (const float*)d_in[i];
    }
    float* out = (float*)d_out;
    float* loss = out;                           // [B, N]
    float* inc_all = out + (size_t)NB * NN;      // [N, N]

    cudaFuncSetAttribute(k_gemm, cudaFuncAttributeMaxDynamicSharedMemorySize, SMEM_B);

    k_prep<<<NN, 256>>>(inc, inc_all);
    k_xt<<<dim3(NN / 64, NB), 256>>>(X);
    k_xproj<<<(NB * NN * 4) / 256, 256>>>(X, rp);
    k_gemm<<<dim3(NN / BM, (NB * ND) / BN), 256, SMEM_B>>>(loss);
}

// round 13
// speedup vs baseline: 1.0360x; 1.0353x over previous
#include <cuda_runtime.h>
#include <cuda_bf16.h>
#include <stdint.h>

#define NN 4096
#define NB 16
#define ND 64

// GEMM tiling: C[4096,1024] = W[4096,4096] @ Xt^T, Xt[n=b*64+d][k]
#define BM 256
#define BN 128
#define BK 64
#define STAGES 3
#define KT (NN / BK)                 // 64
#define ASTR 72                      // padded row stride (elems): 144B, %16==0
#define A_TILE_B (BM * ASTR * 2)     // 36864
#define B_TILE_B (BN * ASTR * 2)     // 18432
#define STAGE_B (A_TILE_B + B_TILE_B) // 55296
#define SMEM_B (STAGES * STAGE_B)    // 165888 (<= 227KB, occ 1)

// ---------------- scratch (device globals: allocation-free) ----------------
static __device__ __align__(16) __nv_bfloat16 g_Wbf[(size_t)NN * NN];        // 32 MB, diag=0
static __device__ __align__(16) __nv_bfloat16 g_Xt[(size_t)NB * ND * NN];    // 8 MB, [b*64+d][k]
static __device__ __align__(16) float         g_Xproj[(size_t)NB * NN * ND]; // 16.8 MB
static __device__ float2        g_l12[NN];

// ---------------- PTX helpers ----------------------------------------------
#define CP_ASYNC16(dst, src) \
    asm volatile("cp.async.cg.shared.global [%0], [%1], 16;" :: "r"(dst), "l"(src))
#define CP_COMMIT() asm volatile("cp.async.commit_group;" ::: "memory")
#define CP_WAIT(n)  asm volatile("cp.async.wait_group %0;" :: "n"(n) : "memory")

__device__ __forceinline__ uint32_t smem_u32(const void* p) {
    uint32_t a;
    asm("{ .reg .u64 t; cvta.to.shared.u64 t, %1; cvt.u32.u64 %0, t; }" : "=r"(a) : "l"(p));
    return a;
}
__device__ __forceinline__ void ldsm4(uint32_t a, uint32_t& r0, uint32_t& r1, uint32_t& r2, uint32_t& r3) {
    asm volatile("ldmatrix.sync.aligned.m8n8.x4.shared.b16 {%0,%1,%2,%3},[%4];"
                 : "=r"(r0), "=r"(r1), "=r"(r2), "=r"(r3) : "r"(a));
}
// non-volatile: pure register dataflow (ordering via data deps)
__device__ __forceinline__ void mma_bf16(float* c, uint32_t a0, uint32_t a1, uint32_t a2, uint32_t a3,
                                         uint32_t b0, uint32_t b1) {
    asm("mma.sync.aligned.m16n8k16.row.col.f32.bf16.bf16.f32 "
        "{%0,%1,%2,%3}, {%4,%5,%6,%7}, {%8,%9}, {%0,%1,%2,%3};"
        : "+f"(c[0]), "+f"(c[1]), "+f"(c[2]), "+f"(c[3])
        : "r"(a0), "r"(a1), "r"(a2), "r"(a3), "r"(b0), "r"(b1));
}
__device__ __forceinline__ uint32_t pack_bf2(float a, float b) {
    __nv_bfloat162 p = __floats2bfloat162_rn(a, b);
    return *(uint32_t*)&p;
}

// ---------------- kernel 1: threshold/scatter W, incidence_all, l1/l2 ------
// (best-measured version — scalar near-coalesced; prep is DRAM-bound, closed)
__global__ void k_prep(const float* __restrict__ inc, float* __restrict__ inc_all) {
    int i = blockIdx.x;
    const float* row = inc + (size_t)i * (NN - 1);
    float* orow = inc_all + (size_t)i * NN;
    __nv_bfloat16* wrow = g_Wbf + (size_t)i * NN;

    float lmax = 0.0f, lsq = 0.0f;
    for (int j = threadIdx.x; j < NN - 1; j += blockDim.x) {
        float v = row[j];
        float w = (v > 0.01f) ? v : 0.0f;
        int fc = j + (j >= i);
        orow[fc] = w;
        wrow[fc] = __float2bfloat16(w);
        lmax = fmaxf(lmax, w);
        lsq += w * w;
    }
    if (threadIdx.x == 0) {
        orow[i] = 1.0f;
        wrow[i] = __float2bfloat16(0.0f);
    }
    #pragma unroll
    for (int o = 16; o > 0; o >>= 1) {
        lmax = fmaxf(lmax, __shfl_xor_sync(0xffffffffu, lmax, o));
        lsq += __shfl_xor_sync(0xffffffffu, lsq, o);
    }
    __shared__ float sm[8], ss[8];
    int wid = threadIdx.x >> 5, lane = threadIdx.x & 31;
    if (lane == 0) { sm[wid] = lmax; ss[wid] = lsq; }
    __syncthreads();
    if (threadIdx.x == 0) {
        float m = sm[0], q = ss[0];
        #pragma unroll
        for (int k = 1; k < 8; k++) { m = fmaxf(m, sm[k]); q += ss[k]; }
        g_l12[i] = make_float2(m, sqrtf(q));
    }
}

// ---------------- kernel 2: transpose X -> Xt bf16 [b*64+d][k] -------------
#define XS 68
__global__ void k_xt(const float* __restrict__ X) {
    __shared__ __align__(16) float s[64 * XS];
    int k0 = blockIdx.x * 64, b = blockIdx.y;
    int t = threadIdx.x;
    {
        int tr = t >> 2, tc = (t & 3) * 16;
        const float* src = X + ((size_t)b * NN + k0 + tr) * ND + tc;
        float4 v0 = ((const float4*)src)[0];
        float4 v1 = ((const float4*)src)[1];
        float4 v2 = ((const float4*)src)[2];
        float4 v3 = ((const float4*)src)[3];
        float* sr = s + tr * XS + tc;
        *(float4*)(sr + 0)  = v0;
        *(float4*)(sr + 4)  = v1;
        *(float4*)(sr + 8)  = v2;
        *(float4*)(sr + 12) = v3;
    }
    __syncthreads();
    {
        int d = t >> 2, kc = (t & 3) * 16;
        const float* sc = s + kc * XS + d;
        uint4 u0, u1;
        u0.x = pack_bf2(sc[0 * XS],  sc[1 * XS]);
        u0.y = pack_bf2(sc[2 * XS],  sc[3 * XS]);
        u0.z = pack_bf2(sc[4 * XS],  sc[5 * XS]);
        u0.w = pack_bf2(sc[6 * XS],  sc[7 * XS]);
        u1.x = pack_bf2(sc[8 * XS],  sc[9 * XS]);
        u1.y = pack_bf2(sc[10 * XS], sc[11 * XS]);
        u1.z = pack_bf2(sc[12 * XS], sc[13 * XS]);
        u1.w = pack_bf2(sc[14 * XS], sc[15 * XS]);
        __nv_bfloat16* dst = g_Xt + ((size_t)b * ND + d) * NN + k0 + kc;
        ((uint4*)dst)[0] = u0;
        ((uint4*)dst)[1] = u1;
    }
}

// ---------------- kernel 3: X_proj = X @ r_proj (fp32 exact) ---------------
__global__ void k_xproj(const float* __restrict__ X, const float* __restrict__ rp) {
    __shared__ float rps[ND * ND];
    for (int t = threadIdx.x; t < ND * ND / 4; t += blockDim.x)
        ((float4*)rps)[t] = ((const float4*)rp)[t];
    __syncthreads();

    int gt = blockIdx.x * blockDim.x + threadIdx.x;
    int row = gt >> 2;
    int d0 = (gt & 3) * 16;
    const float* xr = X + (size_t)row * ND;

    float acc[16];
    #pragma unroll
    for (int i = 0; i < 16; i++) acc[i] = 0.0f;

    #pragma unroll 4
    for (int e = 0; e < ND; e++) {
        float xe = __ldg(&xr[e]);
        const float* rr = rps + e * ND + d0;
        #pragma unroll
        for (int i = 0; i < 16; i++) acc[i] += xe * rr[i];
    }
    float* o = g_Xproj + (size_t)row * ND + d0;
    #pragma unroll
    for (int i = 0; i < 4; i++)
        ((float4*)o)[i] = make_float4(acc[4*i], acc[4*i+1], acc[4*i+2], acc[4*i+3]);
}

// ---------------- kernel 4: HMMA GEMM (fused N=1024) + loss epilogue -------
// 512 threads, 16 warps 4x4 (warp tile 64x32); BM=256, one CTA per SM (occ 1),
// grid 16x8 = 128 CTAs: uniform single wave, no SM pipe-sharing imbalance.
__global__ void __launch_bounds__(512, 1) k_gemm(float* __restrict__ out_loss) {
    extern __shared__ char dsm[];
    const uint32_t sbase = smem_u32(dsm);

    const int tid = threadIdx.x, wid = tid >> 5, lane = tid & 31;
    const int wm = wid >> 2, wn = wid & 3;           // 4x4 warps, 64x32 each
    const int mbase = wm * 64, nbase = wn * 32;
    const int g = lane >> 2, t4 = lane & 3;
    const int lrow = lane & 15, lcol = (lane >> 4) * 8;

    const int m0 = blockIdx.x * BM;
    const int n0 = blockIdx.y * BN;                  // n = b*64+d space

    const __nv_bfloat16* Ag = g_Wbf + (size_t)m0 * NN;
    const __nv_bfloat16* Bg = g_Xt + (size_t)n0 * NN;

    // cp.async: A 2048 chunks (4/thread), B 1024 chunks (2/thread)
    const int ldrow = tid >> 3;            // 0..63 (+64i)
    const int ldcol = (tid & 7) * 8;       // 0..56
    const uint32_t ld_off = (uint32_t)(ldrow * (ASTR * 2) + ldcol * 2);

    const uint32_t a_inv = (uint32_t)((mbase + lrow) * (ASTR * 2) + lcol * 2);
    const uint32_t b_inv = (uint32_t)((nbase + lrow) * (ASTR * 2) + lcol * 2) + A_TILE_B;

    #define LOAD_STAGE(sb_, kc_) do {                                        \
        const __nv_bfloat16* _ag = Ag + (size_t)(kc_) * BK + ldcol;          \
        const __nv_bfloat16* _bg = Bg + (size_t)(kc_) * BK + ldcol;          \
        _Pragma("unroll")                                                    \
        for (int _i = 0; _i < 4; _i++) {                                     \
            uint32_t _o = ld_off + (uint32_t)(_i * 64 * (ASTR * 2));         \
            CP_ASYNC16((sb_) + _o, _ag + (size_t)(ldrow + _i * 64) * NN);    \
        }                                                                    \
        _Pragma("unroll")                                                    \
        for (int _i = 0; _i < 2; _i++) {                                     \
            uint32_t _o = ld_off + (uint32_t)(_i * 64 * (ASTR * 2));         \
            CP_ASYNC16((sb_) + A_TILE_B + _o,                                \
                       _bg + (size_t)(ldrow + _i * 64) * NN);                \
        }                                                                    \
        CP_COMMIT();                                                         \
    } while (0)

    float acc[4][4][4];
    #pragma unroll
    for (int i = 0; i < 4; i++)
        #pragma unroll
        for (int j = 0; j < 4; j++)
            #pragma unroll
            for (int k = 0; k < 4; k++) acc[i][j][k] = 0.0f;

    LOAD_STAGE(sbase, 0);
    LOAD_STAGE(sbase + STAGE_B, 1);

    uint32_t soff = 0;
    uint32_t poff = 2 * STAGE_B;
    #pragma unroll 1
    for (int kt = 0; kt < KT; kt++) {
        CP_WAIT(1);
        __syncthreads();

        if (kt + 2 < KT) LOAD_STAGE(sbase + poff, kt + 2);
        else CP_COMMIT();               // keep group-count invariant

        const uint32_t ab = sbase + soff + a_inv;
        const uint32_t bb = sbase + soff + b_inv;
        #pragma unroll
        for (int ks = 0; ks < 4; ks++) {
            const uint32_t kb = (uint32_t)(ks * 32);
            uint32_t ar[4][4], br[2][4];
            #pragma unroll
            for (int mf = 0; mf < 4; mf++)
                ldsm4(ab + kb + (uint32_t)(mf * 16 * (ASTR * 2)),
                      ar[mf][0], ar[mf][1], ar[mf][2], ar[mf][3]);
            #pragma unroll
            for (int p = 0; p < 2; p++)
                ldsm4(bb + kb + (uint32_t)(p * 16 * (ASTR * 2)),
                      br[p][0], br[p][1], br[p][2], br[p][3]);
            #pragma unroll
            for (int mf = 0; mf < 4; mf++)
                #pragma unroll
                for (int p = 0; p < 2; p++) {
                    mma_bf16(acc[mf][2 * p + 0], ar[mf][0], ar[mf][1], ar[mf][2], ar[mf][3],
                             br[p][0], br[p][2]);
                    mma_bf16(acc[mf][2 * p + 1], ar[mf][0], ar[mf][1], ar[mf][2], ar[mf][3],
                             br[p][1], br[p][3]);
                }
        }

        soff += STAGE_B; if (soff == STAGES * STAGE_B) soff = 0;
        poff += STAGE_B; if (poff == STAGES * STAGE_B) poff = 0;
    }

    // ---- epilogue: warp covers rows mbase..+63, cols nbase..+31 ----
    const int b = (n0 + nbase) >> 6;
    const int dbase = nbase & 63;
    float rs[8];
    #pragma unroll
    for (int i = 0; i < 8; i++) rs[i] = 0.0f;

    #pragma unroll
    for (int mf = 0; mf < 4; mf++) {
        #pragma unroll
        for (int h = 0; h < 2; h++) {
            const int r = m0 + mbase + mf * 16 + h * 8 + g;
            const float* xp = g_Xproj + ((size_t)b * NN + r) * ND + dbase;
            float a = 0.0f;
            #pragma unroll
            for (int nf = 0; nf < 4; nf++) {
                float2 v = *(const float2*)(xp + nf * 8 + 2 * t4);
                float d0 = v.x - acc[mf][nf][h * 2 + 0];
                float d1 = v.y - acc[mf][nf][h * 2 + 1];
                a += d0 * d0 + d1 * d1;
            }
            rs[mf * 2 + h] = a;
        }
    }
    #pragma unroll
    for (int i = 0; i < 8; i++) {
        rs[i] += __shfl_xor_sync(0xffffffffu, rs[i], 1);
        rs[i] += __shfl_xor_sync(0xffffffffu, rs[i], 2);
    }

    // combine wn pairs through smem (pipeline buffers dead now)
    __syncthreads();
    float* red = (float*)dsm;       // [wm=4][wn=4][64] = 1024 floats
    if (t4 == 0) {
        #pragma unroll
        for (int i = 0; i < 8; i++) {
            const int rloc = (i >> 1) * 16 + (i & 1) * 8 + g;
            red[(wm * 4 + wn) * 64 + rloc] = rs[i];
        }
    }
    __syncthreads();
    {
        const int bsel = tid >> 8;            // 0,1: batch within tile
        const int rl = tid & 255;             // row within BM=256
        const int wmx = rl >> 6, rloc = rl & 63;
        const float s2 = red[(wmx * 4 + bsel * 2) * 64 + rloc] +
                         red[(wmx * 4 + bsel * 2 + 1) * 64 + rloc];
        const int row = m0 + rl;
        const int batch = blockIdx.y * 2 + bsel;
        const float2 l = g_l12[row];
        out_loss[(size_t)batch * NN + row] = 0.2f * sqrtf(s2) + l.x + 0.001f * l.y;
    }
}

// ---------------- launch ----------------------------------------------------
extern "C" void kernel_launch(void* const* d_in, const int* in_sizes, int n_in,
                              void* d_out, int out_size) {
    const float *X = nullptr, *rp = nullptr, *inc = nullptr;
    for (int i = 0; i < n_in; i++) {
        if (in_sizes[i] == NB * NN * ND)       X   = (const float*)d_in[i];
        else if (in_sizes[i] == ND * ND)       rp  = (const float*)d_in[i];
        else if (in_sizes[i] == NN * (NN - 1)) inc = (const float*)d_in[i];
    }
    float* out = (float*)d_out;
    float* loss = out;                           // [B, N]
    float* inc_all = out + (size_t)NB * NN;      // [N, N]

    cudaFuncSetAttribute(k_gemm, cudaFuncAttributeMaxDynamicSharedMemorySize, SMEM_B);

    k_prep<<<NN, 256>>>(inc, inc_all);
    k_xt<<<dim3(NN / 64, NB), 256>>>(X);
    k_xproj<<<(NB * NN * 4) / 256, 256>>>(X, rp);
    k_gemm<<<dim3(NN / BM, (NB * ND) / BN), 512, SMEM_B>>>(loss);
}

// round 14
// speedup vs baseline: 1.2986x; 1.2535x over previous
#include <cuda_runtime.h>
#include <cuda_bf16.h>
#include <stdint.h>

#define NN 4096
#define NB 16
#define ND 64

// GEMM tiling: C[4096,1024] = W[4096,4096] @ Xt^T, Xt[n=b*64+d][k]
#define BM 256
#define BN 128
#define BK 64
#define STAGES 3
#define KT (NN / BK)                 // 64
#define ASTR 72                      // padded row stride (elems): 144B, %16==0
#define A_TILE_B (BM * ASTR * 2)     // 36864
#define B_TILE_B (BN * ASTR * 2)     // 18432
#define STAGE_B (A_TILE_B + B_TILE_B) // 55296
#define SMEM_B (STAGES * STAGE_B)    // 165888 (occ 1)

// ---------------- scratch (device globals: allocation-free) ----------------
static __device__ __align__(16) __nv_bfloat16 g_Wbf[(size_t)NN * NN];        // 32 MB, diag=0
static __device__ __align__(16) __nv_bfloat16 g_Xt[(size_t)NB * ND * NN];    // 8 MB, [b*64+d][k]
static __device__ __align__(16) float         g_Xproj[(size_t)NB * NN * ND]; // 16.8 MB
static __device__ float2        g_l12[NN];

// ---------------- PTX helpers ----------------------------------------------
#define CP_ASYNC16(dst, src) \
    asm volatile("cp.async.cg.shared.global [%0], [%1], 16;" :: "r"(dst), "l"(src))
#define CP_COMMIT() asm volatile("cp.async.commit_group;" ::: "memory")
#define CP_WAIT(n)  asm volatile("cp.async.wait_group %0;" :: "n"(n) : "memory")

__device__ __forceinline__ uint32_t smem_u32(const void* p) {
    uint32_t a;
    asm("{ .reg .u64 t; cvta.to.shared.u64 t, %1; cvt.u32.u64 %0, t; }" : "=r"(a) : "l"(p));
    return a;
}
__device__ __forceinline__ void ldsm4(uint32_t a, uint32_t& r0, uint32_t& r1, uint32_t& r2, uint32_t& r3) {
    asm volatile("ldmatrix.sync.aligned.m8n8.x4.shared.b16 {%0,%1,%2,%3},[%4];"
                 : "=r"(r0), "=r"(r1), "=r"(r2), "=r"(r3) : "r"(a));
}
// non-volatile: pure register dataflow (ordering via data deps)
__device__ __forceinline__ void mma_bf16(float* c, uint32_t a0, uint32_t a1, uint32_t a2, uint32_t a3,
                                         uint32_t b0, uint32_t b1) {
    asm("mma.sync.aligned.m16n8k16.row.col.f32.bf16.bf16.f32 "
        "{%0,%1,%2,%3}, {%4,%5,%6,%7}, {%8,%9}, {%0,%1,%2,%3};"
        : "+f"(c[0]), "+f"(c[1]), "+f"(c[2]), "+f"(c[3])
        : "r"(a0), "r"(a1), "r"(a2), "r"(a3), "r"(b0), "r"(b1));
}
__device__ __forceinline__ uint32_t pack_bf2(float a, float b) {
    __nv_bfloat162 p = __floats2bfloat162_rn(a, b);
    return *(uint32_t*)&p;
}

// ---------------- kernel 1: threshold/scatter W, incidence_all, l1/l2 ------
// (best-measured version — scalar near-coalesced; prep is DRAM-bound, closed)
__global__ void k_prep(const float* __restrict__ inc, float* __restrict__ inc_all) {
    int i = blockIdx.x;
    const float* row = inc + (size_t)i * (NN - 1);
    float* orow = inc_all + (size_t)i * NN;
    __nv_bfloat16* wrow = g_Wbf + (size_t)i * NN;

    float lmax = 0.0f, lsq = 0.0f;
    for (int j = threadIdx.x; j < NN - 1; j += blockDim.x) {
        float v = row[j];
        float w = (v > 0.01f) ? v : 0.0f;
        int fc = j + (j >= i);
        orow[fc] = w;
        wrow[fc] = __float2bfloat16(w);
        lmax = fmaxf(lmax, w);
        lsq += w * w;
    }
    if (threadIdx.x == 0) {
        orow[i] = 1.0f;
        wrow[i] = __float2bfloat16(0.0f);
    }
    #pragma unroll
    for (int o = 16; o > 0; o >>= 1) {
        lmax = fmaxf(lmax, __shfl_xor_sync(0xffffffffu, lmax, o));
        lsq += __shfl_xor_sync(0xffffffffu, lsq, o);
    }
    __shared__ float sm[8], ss[8];
    int wid = threadIdx.x >> 5, lane = threadIdx.x & 31;
    if (lane == 0) { sm[wid] = lmax; ss[wid] = lsq; }
    __syncthreads();
    if (threadIdx.x == 0) {
        float m = sm[0], q = ss[0];
        #pragma unroll
        for (int k = 1; k < 8; k++) { m = fmaxf(m, sm[k]); q += ss[k]; }
        g_l12[i] = make_float2(m, sqrtf(q));
    }
}

// ---------------- kernel 2: transpose X -> Xt bf16 [b*64+d][k] -------------
#define XS 68
__global__ void k_xt(const float* __restrict__ X) {
    __shared__ __align__(16) float s[64 * XS];
    int k0 = blockIdx.x * 64, b = blockIdx.y;
    int t = threadIdx.x;
    {
        int tr = t >> 2, tc = (t & 3) * 16;
        const float* src = X + ((size_t)b * NN + k0 + tr) * ND + tc;
        float4 v0 = ((const float4*)src)[0];
        float4 v1 = ((const float4*)src)[1];
        float4 v2 = ((const float4*)src)[2];
        float4 v3 = ((const float4*)src)[3];
        float* sr = s + tr * XS + tc;
        *(float4*)(sr + 0)  = v0;
        *(float4*)(sr + 4)  = v1;
        *(float4*)(sr + 8)  = v2;
        *(float4*)(sr + 12) = v3;
    }
    __syncthreads();
    {
        int d = t >> 2, kc = (t & 3) * 16;
        const float* sc = s + kc * XS + d;
        uint4 u0, u1;
        u0.x = pack_bf2(sc[0 * XS],  sc[1 * XS]);
        u0.y = pack_bf2(sc[2 * XS],  sc[3 * XS]);
        u0.z = pack_bf2(sc[4 * XS],  sc[5 * XS]);
        u0.w = pack_bf2(sc[6 * XS],  sc[7 * XS]);
        u1.x = pack_bf2(sc[8 * XS],  sc[9 * XS]);
        u1.y = pack_bf2(sc[10 * XS], sc[11 * XS]);
        u1.z = pack_bf2(sc[12 * XS], sc[13 * XS]);
        u1.w = pack_bf2(sc[14 * XS], sc[15 * XS]);
        __nv_bfloat16* dst = g_Xt + ((size_t)b * ND + d) * NN + k0 + kc;
        ((uint4*)dst)[0] = u0;
        ((uint4*)dst)[1] = u1;
    }
}

// ---------------- kernel 3: X_proj = X @ r_proj (fp32, 4-row blocked) ------
// Thread computes a 4-row x 16-col output block: LDS traffic per output /4,
// X rows loaded as float4 with warp-level address dedup (4 lanes share a row).
__global__ void __launch_bounds__(256) k_xproj(const float* __restrict__ X,
                                               const float* __restrict__ rp) {
    __shared__ __align__(16) float rps[ND * ND];
    for (int t = threadIdx.x; t < ND * ND / 4; t += 256)
        ((float4*)rps)[t] = ((const float4*)rp)[t];
    __syncthreads();

    const int gt = blockIdx.x * 256 + threadIdx.x;   // 65536 threads
    const int rg = gt >> 2;                           // 4-row group
    const int d0 = (gt & 3) * 16;                     // col chunk
    const int r0 = rg * 4;
    const float* xr = X + (size_t)r0 * ND;

    float acc[4][16];
    #pragma unroll
    for (int i = 0; i < 4; i++)
        #pragma unroll
        for (int j = 0; j < 16; j++) acc[i][j] = 0.0f;

    #pragma unroll 2
    for (int e4 = 0; e4 < ND; e4 += 4) {
        float4 xv[4];
        #pragma unroll
        for (int i = 0; i < 4; i++)
            xv[i] = *(const float4*)(xr + i * ND + e4);

        #pragma unroll
        for (int ee = 0; ee < 4; ee++) {
            const float* rr = rps + (e4 + ee) * ND + d0;
            float4 rv0 = ((const float4*)rr)[0];
            float4 rv1 = ((const float4*)rr)[1];
            float4 rv2 = ((const float4*)rr)[2];
            float4 rv3 = ((const float4*)rr)[3];
            #pragma unroll
            for (int i = 0; i < 4; i++) {
                const float xe = (ee == 0) ? xv[i].x : (ee == 1) ? xv[i].y
                               : (ee == 2) ? xv[i].z : xv[i].w;
                acc[i][0]  += xe * rv0.x;  acc[i][1]  += xe * rv0.y;
                acc[i][2]  += xe * rv0.z;  acc[i][3]  += xe * rv0.w;
                acc[i][4]  += xe * rv1.x;  acc[i][5]  += xe * rv1.y;
                acc[i][6]  += xe * rv1.z;  acc[i][7]  += xe * rv1.w;
                acc[i][8]  += xe * rv2.x;  acc[i][9]  += xe * rv2.y;
                acc[i][10] += xe * rv2.z;  acc[i][11] += xe * rv2.w;
                acc[i][12] += xe * rv3.x;  acc[i][13] += xe * rv3.y;
                acc[i][14] += xe * rv3.z;  acc[i][15] += xe * rv3.w;
            }
        }
    }

    #pragma unroll
    for (int i = 0; i < 4; i++) {
        float* o = g_Xproj + (size_t)(r0 + i) * ND + d0;
        #pragma unroll
        for (int q = 0; q < 4; q++)
            ((float4*)o)[q] = make_float4(acc[i][4*q], acc[i][4*q+1],
                                          acc[i][4*q+2], acc[i][4*q+3]);
    }
}

// ---------------- kernel 4: HMMA GEMM (fused N=1024) + loss epilogue -------
// 512 threads, 16 warps 4x4 (warp tile 64x32); BM=256, occ 1, 128-CTA uniform wave.
__global__ void __launch_bounds__(512, 1) k_gemm(float* __restrict__ out_loss) {
    extern __shared__ char dsm[];
    const uint32_t sbase = smem_u32(dsm);

    const int tid = threadIdx.x, wid = tid >> 5, lane = tid & 31;
    const int wm = wid >> 2, wn = wid & 3;           // 4x4 warps, 64x32 each
    const int mbase = wm * 64, nbase = wn * 32;
    const int g = lane >> 2, t4 = lane & 3;
    const int lrow = lane & 15, lcol = (lane >> 4) * 8;

    const int m0 = blockIdx.x * BM;
    const int n0 = blockIdx.y * BN;                  // n = b*64+d space

    const __nv_bfloat16* Ag = g_Wbf + (size_t)m0 * NN;
    const __nv_bfloat16* Bg = g_Xt + (size_t)n0 * NN;

    const int ldrow = tid >> 3;            // 0..63 (+64i)
    const int ldcol = (tid & 7) * 8;       // 0..56
    const uint32_t ld_off = (uint32_t)(ldrow * (ASTR * 2) + ldcol * 2);

    const uint32_t a_inv = (uint32_t)((mbase + lrow) * (ASTR * 2) + lcol * 2);
    const uint32_t b_inv = (uint32_t)((nbase + lrow) * (ASTR * 2) + lcol * 2) + A_TILE_B;

    #define LOAD_STAGE(sb_, kc_) do {                                        \
        const __nv_bfloat16* _ag = Ag + (size_t)(kc_) * BK + ldcol;          \
        const __nv_bfloat16* _bg = Bg + (size_t)(kc_) * BK + ldcol;          \
        _Pragma("unroll")                                                    \
        for (int _i = 0; _i < 4; _i++) {                                     \
            uint32_t _o = ld_off + (uint32_t)(_i * 64 * (ASTR * 2));         \
            CP_ASYNC16((sb_) + _o, _ag + (size_t)(ldrow + _i * 64) * NN);    \
        }                                                                    \
        _Pragma("unroll")                                                    \
        for (int _i = 0; _i < 2; _i++) {                                     \
            uint32_t _o = ld_off + (uint32_t)(_i * 64 * (ASTR * 2));         \
            CP_ASYNC16((sb_) + A_TILE_B + _o,                                \
                       _bg + (size_t)(ldrow + _i * 64) * NN);                \
        }                                                                    \
        CP_COMMIT();                                                         \
    } while (0)

    float acc[4][4][4];
    #pragma unroll
    for (int i = 0; i < 4; i++)
        #pragma unroll
        for (int j = 0; j < 4; j++)
            #pragma unroll
            for (int k = 0; k < 4; k++) acc[i][j][k] = 0.0f;

    LOAD_STAGE(sbase, 0);
    LOAD_STAGE(sbase + STAGE_B, 1);

    uint32_t soff = 0;
    uint32_t poff = 2 * STAGE_B;
    #pragma unroll 1
    for (int kt = 0; kt < KT; kt++) {
        CP_WAIT(1);
        __syncthreads();

        if (kt + 2 < KT) LOAD_STAGE(sbase + poff, kt + 2);
        else CP_COMMIT();               // keep group-count invariant

        const uint32_t ab = sbase + soff + a_inv;
        const uint32_t bb = sbase + soff + b_inv;
        #pragma unroll
        for (int ks = 0; ks < 4; ks++) {
            const uint32_t kb = (uint32_t)(ks * 32);
            uint32_t ar[4][4], br[2][4];
            #pragma unroll
            for (int mf = 0; mf < 4; mf++)
                ldsm4(ab + kb + (uint32_t)(mf * 16 * (ASTR * 2)),
                      ar[mf][0], ar[mf][1], ar[mf][2], ar[mf][3]);
            #pragma unroll
            for (int p = 0; p < 2; p++)
                ldsm4(bb + kb + (uint32_t)(p * 16 * (ASTR * 2)),
                      br[p][0], br[p][1], br[p][2], br[p][3]);
            #pragma unroll
            for (int mf = 0; mf < 4; mf++)
                #pragma unroll
                for (int p = 0; p < 2; p++) {
                    mma_bf16(acc[mf][2 * p + 0], ar[mf][0], ar[mf][1], ar[mf][2], ar[mf][3],
                             br[p][0], br[p][2]);
                    mma_bf16(acc[mf][2 * p + 1], ar[mf][0], ar[mf][1], ar[mf][2], ar[mf][3],
                             br[p][1], br[p][3]);
                }
        }

        soff += STAGE_B; if (soff == STAGES * STAGE_B) soff = 0;
        poff += STAGE_B; if (poff == STAGES * STAGE_B) poff = 0;
    }

    // ---- epilogue: warp covers rows mbase..+63, cols nbase..+31 ----
    const int b = (n0 + nbase) >> 6;
    const int dbase = nbase & 63;
    float rs[8];
    #pragma unroll
    for (int i = 0; i < 8; i++) rs[i] = 0.0f;

    #pragma unroll
    for (int mf = 0; mf < 4; mf++) {
        #pragma unroll
        for (int h = 0; h < 2; h++) {
            const int r = m0 + mbase + mf * 16 + h * 8 + g;
            const float* xp = g_Xproj + ((size_t)b * NN + r) * ND + dbase;
            float a = 0.0f;
            #pragma unroll
            for (int nf = 0; nf < 4; nf++) {
                float2 v = *(const float2*)(xp + nf * 8 + 2 * t4);
                float d0 = v.x - acc[mf][nf][h * 2 + 0];
                float d1 = v.y - acc[mf][nf][h * 2 + 1];
                a += d0 * d0 + d1 * d1;
            }
            rs[mf * 2 + h] = a;
        }
    }
    #pragma unroll
    for (int i = 0; i < 8; i++) {
        rs[i] += __shfl_xor_sync(0xffffffffu, rs[i], 1);
        rs[i] += __shfl_xor_sync(0xffffffffu, rs[i], 2);
    }

    __syncthreads();
    float* red = (float*)dsm;       // [wm=4][wn=4][64]
    if (t4 == 0) {
        #pragma unroll
        for (int i = 0; i < 8; i++) {
            const int rloc = (i >> 1) * 16 + (i & 1) * 8 + g;
            red[(wm * 4 + wn) * 64 + rloc] = rs[i];
        }
    }
    __syncthreads();
    {
        const int bsel = tid >> 8;            // 0,1: batch within tile
        const int rl = tid & 255;             // row within BM=256
        const int wmx = rl >> 6, rloc = rl & 63;
        const float s2 = red[(wmx * 4 + bsel * 2) * 64 + rloc] +
                         red[(wmx * 4 + bsel * 2 + 1) * 64 + rloc];
        const int row = m0 + rl;
        const int batch = blockIdx.y * 2 + bsel;
        const float2 l = g_l12[row];
        out_loss[(size_t)batch * NN + row] = 0.2f * sqrtf(s2) + l.x + 0.001f * l.y;
    }
}

// ---------------- launch ----------------------------------------------------
extern "C" void kernel_launch(void* const* d_in, const int* in_sizes, int n_in,
                              void* d_out, int out_size) {
    const float *X = nullptr, *rp = nullptr, *inc = nullptr;
    for (int i = 0; i < n_in; i++) {
        if (in_sizes[i] == NB * NN * ND)       X   = (const float*)d_in[i];
        else if (in_sizes[i] == ND * ND)       rp  = (const float*)d_in[i];
        else if (in_sizes[i] == NN * (NN - 1)) inc = (const float*)d_in[i];
    }
    float* out = (float*)d_out;
    float* loss = out;                           // [B, N]
    float* inc_all = out + (size_t)NB * NN;      // [N, N]

    cudaFuncSetAttribute(k_gemm, cudaFuncAttributeMaxDynamicSharedMemorySize, SMEM_B);

    k_prep<<<NN, 256>>>(inc, inc_all);
    k_xt<<<dim3(NN / 64, NB), 256>>>(X);
    k_xproj<<<(NB * NN) / 256, 256>>>(X, rp);
    k_gemm<<<dim3(NN / BM, (NB * ND) / BN), 512, SMEM_B>>>(loss);
}